// round 11
// baseline (speedup 1.0000x reference)
#include <cuda_runtime.h>
#include <cstdint>

#define NB 256   // batch
#define NH 2048  // hidden
#define NG 6144  // 3*H
#define NT 512   // time steps
#define NO 14    // output classes

#define NBLK 96  // persistent blocks, each owns one 128x128 C tile (2 x 48)
#define NTHR 256 // 8 warps: 2x4 warp grid, each warp 64x32 of C
#define BK 32    // k per staged iteration
#define KITERS (NH / BK)
#define LDA 36   // smem row stride in floats (conflict-free: 36 == 4 mod 32)

// dynamic smem: 8 tiles (Ahi0 Ahi1 Alo0 Alo1 Bhi0 Bhi1 Blo0 Blo1), 128*LDA each
#define TILE_F (128 * LDA)
#define SMEM_DYN (8 * TILE_F * 4)

// ---- device-global scratch (no allocations allowed) ----
__device__ float g_gh[NB * NG];                         // gh scratch, 6 MB
__device__ float g_h[2 * NB * NH];                      // fp32 hidden, ping-pong
__device__ __align__(16) uint32_t g_Whi[NG * NH];       // tf32 hi of W_hh, 50 MB
__device__ __align__(16) uint32_t g_Wlo[NG * NH];       // tf32 lo of W_hh, 50 MB
__device__ __align__(16) uint32_t g_hhi[2 * NB * NH];   // tf32 hi of h, ping-pong
__device__ __align__(16) uint32_t g_hlo[2 * NB * NH];   // tf32 lo of h, ping-pong
__device__ int   g_topi[NB];
__device__ int   g_sel[NB];
__device__ unsigned g_bar_count;
__device__ unsigned g_bar_gen;

// =====================================================================
// helpers
// =====================================================================
__device__ __forceinline__ uint32_t smem_u32(const void* p) {
    uint32_t a;
    asm("{ .reg .u64 t; cvta.to.shared.u64 t, %1; cvt.u32.u64 %0, t; }"
        : "=r"(a) : "l"(p));
    return a;
}

#define CP_ASYNC16(saddr, gptr) \
    asm volatile("cp.async.cg.shared.global [%0], [%1], 16;" \
                 :: "r"(saddr), "l"(gptr) : "memory")
#define CP_COMMIT()  asm volatile("cp.async.commit_group;" ::: "memory")
#define CP_WAIT(n)   asm volatile("cp.async.wait_group %0;" :: "n"(n) : "memory")

// tf32 split: v = hi + lo, both tf32-representable (round-to-nearest)
__device__ __forceinline__ void tf32_split(float v, uint32_t& hi, uint32_t& lo) {
    asm("cvt.rna.tf32.f32 %0, %1;" : "=r"(hi) : "f"(v));
    float rl = v - __uint_as_float(hi);
    asm("cvt.rna.tf32.f32 %0, %1;" : "=r"(lo) : "f"(rl));
}

// C += A(16x8,row) * B(8x8,col)   tf32 -> f32
#define MMA8(c, a0, a1, a2, a3, b0, b1) \
    asm volatile("mma.sync.aligned.m16n8k8.row.col.f32.tf32.tf32.f32 " \
        "{%0,%1,%2,%3},{%4,%5,%6,%7},{%8,%9},{%0,%1,%2,%3};" \
        : "+f"((c)[0]), "+f"((c)[1]), "+f"((c)[2]), "+f"((c)[3]) \
        : "r"(a0), "r"(a1), "r"(a2), "r"(a3), "r"(b0), "r"(b1))

// =====================================================================
// Software grid barrier (all NBLK blocks co-resident; 96 <= 148 SMs)
// =====================================================================
__device__ __forceinline__ void grid_bar()
{
    __syncthreads();
    if (threadIdx.x == 0) {
        __threadfence();
        unsigned gen = *(volatile unsigned*)&g_bar_gen;
        unsigned arr = atomicAdd(&g_bar_count, 1u);
        if (arr == NBLK - 1) {
            *(volatile unsigned*)&g_bar_count = 0u;
            __threadfence();
            *(volatile unsigned*)&g_bar_gen = gen + 1u;
        } else {
            while (*(volatile unsigned*)&g_bar_gen == gen) { __nanosleep(64); }
        }
        __threadfence();
    }
    __syncthreads();
}

// =====================================================================
// persistent kernel for the full 512-step decode (pre-split tf32 GEMM)
// =====================================================================
__global__ __launch_bounds__(NTHR, 1)
void decoder_kernel(const float* __restrict__ enc_h,
                    const float* __restrict__ target,
                    const float* __restrict__ W_ih,
                    const float* __restrict__ W_hh,
                    const float* __restrict__ b_ih,
                    const float* __restrict__ b_hh,
                    const float* __restrict__ W_out,
                    const float* __restrict__ b_out,
                    float* __restrict__ out)
{
    extern __shared__ float smf[];   // 8 tiles of TILE_F floats

    const int tid = threadIdx.x;
    const int w   = tid >> 5;        // warp 0..7
    const int lid = tid & 31;
    const int gid = lid >> 2;        // groupID 0..7
    const int tig = lid & 3;         // thread-in-group 0..3
    const int wm  = w >> 2;          // 0..1 : warp row (64 M each)
    const int wn  = w & 3;           // 0..3 : warp col (32 N each)
    const int blk  = blockIdx.x;
    const int m0   = (blk / 48) * 128;
    const int n0   = (blk % 48) * 128;
    const int gtid = blk * NTHR + tid;
    const int NTOT = NBLK * NTHR;

    const uint32_t sb = smem_u32(smf);

    // ---------------- prologue: split W_hh and enc_h ---------------------
    for (size_t i = (size_t)gtid * 4; i < (size_t)NG * NH; i += (size_t)NTOT * 4) {
        float4 v = *(const float4*)(W_hh + i);
        uint32_t h0, l0, h1, l1, h2, l2, h3, l3;
        tf32_split(v.x, h0, l0); tf32_split(v.y, h1, l1);
        tf32_split(v.z, h2, l2); tf32_split(v.w, h3, l3);
        *(uint4*)(g_Whi + i) = make_uint4(h0, h1, h2, h3);
        *(uint4*)(g_Wlo + i) = make_uint4(l0, l1, l2, l3);
    }
    // enc_h split goes into slot 1 (read by t=0: slot (1-par) = 1)
    for (size_t i = (size_t)gtid * 4; i < (size_t)NB * NH; i += (size_t)NTOT * 4) {
        float4 v = *(const float4*)(enc_h + i);
        uint32_t h0, l0, h1, l1, h2, l2, h3, l3;
        tf32_split(v.x, h0, l0); tf32_split(v.y, h1, l1);
        tf32_split(v.z, h2, l2); tf32_split(v.w, h3, l3);
        *(uint4*)(g_hhi + (size_t)NB * NH + i) = make_uint4(h0, h1, h2, h3);
        *(uint4*)(g_hlo + (size_t)NB * NH + i) = make_uint4(l0, l1, l2, l3);
    }
    grid_bar();

    for (int t = 0; t < NT; t++) {
        const int par = t & 1;
        const float* hprev = (t == 0) ? enc_h : (g_h + (size_t)(1 - par) * NB * NH);
        const size_t aslot = (size_t)(1 - par) * NB * NH;

        // ---------- scan(t-1): block 0, warp 0 (before GEMM loop) -------
        if (t > 0 && blk == 0 && w == 0) {
            int tp[8]; int hit[8]; unsigned chunk = 0;
#pragma unroll
            for (int i = 0; i < 8; i++) {
                tp[i]  = g_topi[lid * 8 + i];
                hit[i] = (tp[i] == NO - 1);
                chunk |= (unsigned)hit[i];
            }
            unsigned inc = chunk;
#pragma unroll
            for (int off = 1; off < 32; off <<= 1) {
                unsigned v = __shfl_up_sync(0xffffffffu, inc, off);
                if (lid >= off) inc |= v;
            }
            unsigned excl = __shfl_up_sync(0xffffffffu, inc, 1);
            unsigned run  = (lid == 0) ? 0u : excl;
#pragma unroll
            for (int i = 0; i < 8; i++) {
                int alive = !(run | (unsigned)hit[i]);
                g_sel[lid * 8 + i] = alive ? tp[i] : -1;
                run |= (unsigned)hit[i];
            }
        }

        // ---------- GEMM: g_gh[m][n] = hprev[m][:] . W_hh[n][:] --------
        {
            const uint32_t* Aih = g_hhi + aslot + (size_t)m0 * NH;
            const uint32_t* Ail = g_hlo + aslot + (size_t)m0 * NH;
            const uint32_t* Bih = g_Whi + (size_t)n0 * NH;
            const uint32_t* Bil = g_Wlo + (size_t)n0 * NH;

            float acc[4][4][4];
#pragma unroll
            for (int i = 0; i < 4; i++)
#pragma unroll
                for (int j = 0; j < 4; j++)
#pragma unroll
                    for (int c = 0; c < 4; c++) acc[i][j][c] = 0.f;

            // stage(p, k0): 4 tiles -> smem buffers p
#define STAGE(p, k0) do {                                                     \
    _Pragma("unroll")                                                         \
    for (int i = 0; i < 4; i++) {                                             \
        int idx = tid + i * NTHR;                                             \
        int row = idx >> 3;                                                   \
        int c4  = (idx & 7) << 2;                                             \
        uint32_t off = (uint32_t)(row * LDA + c4) * 4u;                       \
        size_t gof = (size_t)row * NH + (k0) + c4;                            \
        CP_ASYNC16(sb + (uint32_t)((0 + (p)) * TILE_F) * 4u + off, Aih + gof);\
        CP_ASYNC16(sb + (uint32_t)((2 + (p)) * TILE_F) * 4u + off, Ail + gof);\
        CP_ASYNC16(sb + (uint32_t)((4 + (p)) * TILE_F) * 4u + off, Bih + gof);\
        CP_ASYNC16(sb + (uint32_t)((6 + (p)) * TILE_F) * 4u + off, Bil + gof);\
    }                                                                         \
    CP_COMMIT();                                                              \
} while (0)

            STAGE(0, 0);

            for (int it = 0; it < KITERS; it++) {
                const int p = it & 1;
                if (it + 1 < KITERS) {
                    STAGE(p ^ 1, (it + 1) * BK);
                    CP_WAIT(1);
                } else {
                    CP_WAIT(0);
                }
                __syncthreads();

                const uint32_t* Ah = (const uint32_t*)(smf + (0 + p) * TILE_F);
                const uint32_t* Al = (const uint32_t*)(smf + (2 + p) * TILE_F);
                const uint32_t* Bh = (const uint32_t*)(smf + (4 + p) * TILE_F);
                const uint32_t* Bl = (const uint32_t*)(smf + (6 + p) * TILE_F);

#pragma unroll
                for (int ks = 0; ks < 4; ks++) {
                    const int kc = ks * 8 + tig;

                    uint32_t bh[4][2], bl[4][2];
#pragma unroll
                    for (int nf = 0; nf < 4; nf++) {
                        const int bb = (wn * 32 + nf * 8 + gid) * LDA + kc;
                        bh[nf][0] = Bh[bb];     bh[nf][1] = Bh[bb + 4];
                        bl[nf][0] = Bl[bb];     bl[nf][1] = Bl[bb + 4];
                    }
#pragma unroll
                    for (int mf = 0; mf < 4; mf++) {
                        const int ab = (wm * 64 + mf * 16 + gid) * LDA + kc;
                        uint32_t ah[4], al[4];
                        ah[0] = Ah[ab];                al[0] = Al[ab];
                        ah[1] = Ah[ab + 8 * LDA];      al[1] = Al[ab + 8 * LDA];
                        ah[2] = Ah[ab + 4];            al[2] = Al[ab + 4];
                        ah[3] = Ah[ab + 8 * LDA + 4];  al[3] = Al[ab + 8 * LDA + 4];
#pragma unroll
                        for (int nf = 0; nf < 4; nf++) {
                            MMA8(acc[mf][nf], al[0], al[1], al[2], al[3],
                                 bh[nf][0], bh[nf][1]);
                            MMA8(acc[mf][nf], ah[0], ah[1], ah[2], ah[3],
                                 bl[nf][0], bl[nf][1]);
                            MMA8(acc[mf][nf], ah[0], ah[1], ah[2], ah[3],
                                 bh[nf][0], bh[nf][1]);
                        }
                    }
                }
                __syncthreads();
            }
#undef STAGE

            // epilogue: registers -> g_gh (float2 stores)
#pragma unroll
            for (int mf = 0; mf < 4; mf++) {
                const int row = m0 + wm * 64 + mf * 16 + gid;
#pragma unroll
                for (int nf = 0; nf < 4; nf++) {
                    const int col = n0 + wn * 32 + nf * 8 + 2 * tig;
                    float2 v0 = make_float2(acc[mf][nf][0], acc[mf][nf][1]);
                    float2 v1 = make_float2(acc[mf][nf][2], acc[mf][nf][3]);
                    *(float2*)(g_gh + (size_t)row * NG + col)       = v0;
                    *(float2*)(g_gh + (size_t)(row + 8) * NG + col) = v1;
                }
            }
        }
        grid_bar();

        // ---------------- gate fusion (+ split of h_new) ----------------
        {
            float* hnew = g_h + (size_t)par * NB * NH;
            const size_t wslot = (size_t)par * NB * NH;
            for (int idx = gtid; idx < NB * NH; idx += NTOT) {
                const int b = idx >> 11;        // / NH
                const int j = idx & (NH - 1);   // % NH

                float ghr = g_gh[(size_t)b * NG + j]          + b_hh[j];
                float ghz = g_gh[(size_t)b * NG + NH + j]     + b_hh[NH + j];
                float ghn = g_gh[(size_t)b * NG + 2 * NH + j] + b_hh[2 * NH + j];
                float gir = b_ih[j], giz = b_ih[NH + j], gin = b_ih[2 * NH + j];

                if (t == 0) {
#pragma unroll
                    for (int o = 0; o < NO; o++) {
                        float xv = fmaxf(target[(size_t)b * NT * NO + o], 0.f);
                        gir = fmaf(xv, W_ih[(size_t)j * NO + o], gir);
                        giz = fmaf(xv, W_ih[(size_t)(NH + j) * NO + o], giz);
                        gin = fmaf(xv, W_ih[(size_t)(2 * NH + j) * NO + o], gin);
                    }
                } else {
                    int s = g_sel[b];
                    if (s >= 0) {
                        gir += W_ih[(size_t)j * NO + s];
                        giz += W_ih[(size_t)(NH + j) * NO + s];
                        gin += W_ih[(size_t)(2 * NH + j) * NO + s];
                    }
                }

                float r  = 1.f / (1.f + expf(-(gir + ghr)));
                float z  = 1.f / (1.f + expf(-(giz + ghz)));
                float n  = tanhf(gin + r * ghn);
                float hp = hprev[(size_t)b * NH + j];
                float hv = (1.f - z) * n + z * hp;
                hnew[idx] = hv;
                uint32_t shi, slo;
                tf32_split(hv, shi, slo);
                g_hhi[wslot + idx] = shi;
                g_hlo[wslot + idx] = slo;
            }
        }
        grid_bar();

        // ------- logits + argmax + log_softmax : one warp per row -------
        {
            const int gw = blk * 8 + w;   // 768 warps, rows 0..255 active
            if (gw < NB) {
                const float* h = g_h + (size_t)par * NB * NH + (size_t)gw * NH;

                float acc[NO];
#pragma unroll
                for (int o = 0; o < NO; o++) acc[o] = 0.f;

                for (int k = lid; k < NH; k += 32) {
                    float hv = h[k];
#pragma unroll
                    for (int o = 0; o < NO; o++)
                        acc[o] = fmaf(hv, W_out[(size_t)o * NH + k], acc[o]);
                }
#pragma unroll
                for (int o = 0; o < NO; o++) {
#pragma unroll
                    for (int off = 16; off > 0; off >>= 1)
                        acc[o] += __shfl_xor_sync(0xffffffffu, acc[o], off);
                }

                if (lid == 0) {
                    float l[NO];
                    float m = -1e30f;
#pragma unroll
                    for (int o = 0; o < NO; o++) { l[o] = acc[o] + b_out[o]; m = fmaxf(m, l[o]); }
                    int   bi = 0;
                    float bv = l[0];
#pragma unroll
                    for (int o = 1; o < NO; o++)
                        if (l[o] > bv) { bv = l[o]; bi = o; }   // first-max = jnp.argmax
                    float s = 0.f;
#pragma unroll
                    for (int o = 0; o < NO; o++) s += expf(l[o] - m);
                    float lse = m + logf(s);
                    float* dst = out + ((size_t)gw * NT + t) * NO;
#pragma unroll
                    for (int o = 0; o < NO; o++) dst[o] = l[o] - lse;
                    g_topi[gw] = bi;
                }
            }
        }
        grid_bar();
    }

    // ---------------- tail: append h_final ------------------------------
    {
        const float* hf = g_h + (size_t)((NT - 1) & 1) * NB * NH;
        float* tail = out + (size_t)NB * NT * NO;
        for (int i = gtid; i < NB * NH / 4; i += NTOT) {
            float4 v = *(const float4*)(hf + (size_t)i * 4);
            *(float4*)(tail + (size_t)i * 4) = v;
        }
    }
}

// =====================================================================
extern "C" void kernel_launch(void* const* d_in, const int* in_sizes, int n_in,
                              void* d_out, int out_size)
{
    // inputs: 0 encoder_outputs (unused), 1 encoder_hidden, 2 target_tensor,
    //         3 W_ih, 4 W_hh, 5 b_ih, 6 b_hh, 7 W_out, 8 b_out
    const float* enc_h  = (const float*)d_in[1];
    const float* target = (const float*)d_in[2];
    const float* W_ih   = (const float*)d_in[3];
    const float* W_hh   = (const float*)d_in[4];
    const float* b_ih   = (const float*)d_in[5];
    const float* b_hh   = (const float*)d_in[6];
    const float* W_out  = (const float*)d_in[7];
    const float* b_out  = (const float*)d_in[8];
    float* out = (float*)d_out;

    cudaFuncSetAttribute(decoder_kernel,
                         cudaFuncAttributeMaxDynamicSharedMemorySize, SMEM_DYN);

    decoder_kernel<<<NBLK, NTHR, SMEM_DYN>>>(enc_h, target, W_ih, W_hh,
                                             b_ih, b_hh, W_out, b_out, out);
}

// round 12
// speedup vs baseline: 1.3310x; 1.3310x over previous
#include <cuda_runtime.h>
#include <cstdint>

#define NB 256   // batch
#define NH 2048  // hidden
#define NG 6144  // 3*H
#define NT 512   // time steps
#define NO 14    // output classes

#define NBLK 128 // persistent blocks, tile grid 2 (M) x 64 (N)
#define NTHR 256 // 8 warps: 2x4 warp grid, warp tile 64x24
#define BK 32    // k per staged iteration
#define KITERS (NH / BK)
#define LDA 36   // smem row stride floats (36 mod 32 = 4 -> conflict-free frags)

#define TM 128   // block tile M
#define TN 96    // block tile N
#define TA_F (TM * LDA)        // 4608 floats
#define TB_F (TN * LDA)        // 3456 floats
#define ST_F (TA_F + TB_F)     // 8064 floats per stage
#define NSTG 4
#define SMEM_DYN (NSTG * ST_F * 4)   // 129024 B

// ---- device-global scratch (no allocations allowed) ----
__device__ __align__(16) float g_gh[NB * NG];     // gh scratch, 6 MB
__device__ __align__(16) float g_h[2 * NB * NH];  // ping-pong hidden state
__device__ int   g_topi[NB];
__device__ unsigned g_bar_count;
__device__ unsigned g_bar_gen;

// =====================================================================
// helpers
// =====================================================================
__device__ __forceinline__ uint32_t smem_u32(const void* p) {
    uint32_t a;
    asm("{ .reg .u64 t; cvta.to.shared.u64 t, %1; cvt.u32.u64 %0, t; }"
        : "=r"(a) : "l"(p));
    return a;
}

#define CP_ASYNC16(saddr, gptr) \
    asm volatile("cp.async.cg.shared.global [%0], [%1], 16;" \
                 :: "r"(saddr), "l"(gptr) : "memory")
#define CP_COMMIT()  asm volatile("cp.async.commit_group;" ::: "memory")
#define CP_WAIT(n)   asm volatile("cp.async.wait_group %0;" :: "n"(n) : "memory")

// tf32 split: v = hi + lo, both tf32-representable (round-to-nearest)
__device__ __forceinline__ void tf32_split(float v, uint32_t& hi, uint32_t& lo) {
    asm("cvt.rna.tf32.f32 %0, %1;" : "=r"(hi) : "f"(v));
    float rl = v - __uint_as_float(hi);
    asm("cvt.rna.tf32.f32 %0, %1;" : "=r"(lo) : "f"(rl));
}

// C += A(16x8,row) * B(8x8,col)   tf32 -> f32
#define MMA8(c, a0, a1, a2, a3, b0, b1) \
    asm volatile("mma.sync.aligned.m16n8k8.row.col.f32.tf32.tf32.f32 " \
        "{%0,%1,%2,%3},{%4,%5,%6,%7},{%8,%9},{%0,%1,%2,%3};" \
        : "+f"((c)[0]), "+f"((c)[1]), "+f"((c)[2]), "+f"((c)[3]) \
        : "r"(a0), "r"(a1), "r"(a2), "r"(a3), "r"(b0), "r"(b1))

// =====================================================================
// Software grid barrier (all NBLK blocks co-resident; 128 <= 148 SMs)
// =====================================================================
__device__ __forceinline__ void grid_bar()
{
    __syncthreads();
    if (threadIdx.x == 0) {
        __threadfence();
        unsigned gen = *(volatile unsigned*)&g_bar_gen;
        unsigned arr = atomicAdd(&g_bar_count, 1u);
        if (arr == NBLK - 1) {
            *(volatile unsigned*)&g_bar_count = 0u;
            __threadfence();
            *(volatile unsigned*)&g_bar_gen = gen + 1u;
        } else {
            while (*(volatile unsigned*)&g_bar_gen == gen) { __nanosleep(64); }
        }
        __threadfence();
    }
    __syncthreads();
}

// =====================================================================
// persistent kernel for the full 512-step decode
// =====================================================================
__global__ __launch_bounds__(NTHR, 1)
void decoder_kernel(const float* __restrict__ enc_h,
                    const float* __restrict__ target,
                    const float* __restrict__ W_ih,
                    const float* __restrict__ W_hh,
                    const float* __restrict__ b_ih,
                    const float* __restrict__ b_hh,
                    const float* __restrict__ W_out,
                    const float* __restrict__ b_out,
                    float* __restrict__ out)
{
    extern __shared__ float smf[];            // NSTG stages of (A | B) tiles
    __shared__ int   s_sel[NB];               // block-local feedback select
    __shared__ float s_red[8][NO];            // logits cross-warp reduce
    __shared__ float s_l[NO];

    const int tid = threadIdx.x;
    const int w   = tid >> 5;        // warp 0..7
    const int lid = tid & 31;
    const int gid = lid >> 2;        // 0..7
    const int tig = lid & 3;         // 0..3
    const int wm  = w >> 2;          // 0..1 : warp row (64 M)
    const int wn  = w & 3;           // 0..3 : warp col (24 N)
    const int blk  = blockIdx.x;
    const int m0   = (blk >> 6) * TM;     // 0 or 128
    const int n0   = (blk & 63) * TN;     // 0..6048
    const int gtid = blk * NTHR + tid;
    const int NTOT = NBLK * NTHR;

    const uint32_t sb = smem_u32(smf);

    for (int t = 0; t < NT; t++) {
        const int par = t & 1;
        const float* hprev = (t == 0) ? enc_h : (g_h + (size_t)(1 - par) * NB * NH);

        // ================= GEMM: g_gh = hprev @ W_hh^T ==================
        {
            const float* Ag = hprev + (size_t)m0 * NH;
            const float* Bg = W_hh  + (size_t)n0 * NH;

            float acc[4][3][4];
#pragma unroll
            for (int i = 0; i < 4; i++)
#pragma unroll
                for (int j = 0; j < 3; j++)
#pragma unroll
                    for (int c = 0; c < 4; c++) acc[i][j][c] = 0.f;

            // stage(bs, k0): A 1024 + B 768 float4 = 1792 = 7 * 256
#define STAGE(bs, k0) do {                                                    \
    const uint32_t sst = sb + (uint32_t)(bs) * (ST_F * 4u);                   \
    _Pragma("unroll")                                                         \
    for (int i = 0; i < 7; i++) {                                             \
        int idx = tid + i * NTHR;                                             \
        if (idx < 1024) {                                                     \
            int row = idx >> 3, c4 = (idx & 7) << 2;                          \
            CP_ASYNC16(sst + (uint32_t)(row * LDA + c4) * 4u,                 \
                       Ag + (size_t)row * NH + (k0) + c4);                    \
        } else {                                                              \
            int jx = idx - 1024;                                              \
            int row = jx >> 3, c4 = (jx & 7) << 2;                            \
            CP_ASYNC16(sst + (uint32_t)(TA_F + row * LDA + c4) * 4u,          \
                       Bg + (size_t)row * NH + (k0) + c4);                    \
        }                                                                     \
    }                                                                         \
    CP_COMMIT();                                                              \
} while (0)

            // prologue: stages 0..2 in flight (3 committed groups)
            STAGE(0, 0);
            STAGE(1, BK);
            STAGE(2, 2 * BK);

            // block-local scan of topi(t-1) -> s_sel (warp 0)
            if (t > 0 && w == 0) {
                int tp[8]; int hit[8]; unsigned chunk = 0;
#pragma unroll
                for (int i = 0; i < 8; i++) {
                    tp[i]  = g_topi[lid * 8 + i];
                    hit[i] = (tp[i] == NO - 1);
                    chunk |= (unsigned)hit[i];
                }
                unsigned inc = chunk;
#pragma unroll
                for (int off = 1; off < 32; off <<= 1) {
                    unsigned v = __shfl_up_sync(0xffffffffu, inc, off);
                    if (lid >= off) inc |= v;
                }
                unsigned excl = __shfl_up_sync(0xffffffffu, inc, 1);
                unsigned run  = (lid == 0) ? 0u : excl;
#pragma unroll
                for (int i = 0; i < 8; i++) {
                    int alive = !(run | (unsigned)hit[i]);
                    s_sel[lid * 8 + i] = alive ? tp[i] : -1;
                    run |= (unsigned)hit[i];
                }
            }

            for (int it = 0; it < KITERS; it++) {
                CP_WAIT(2);           // stage 'it' landed (this thread)
                __syncthreads();      // all threads: data visible, old buf free
                if (it + 3 < KITERS) {
                    STAGE((it + 3) & 3, (it + 3) * BK);
                } else {
                    CP_COMMIT();      // empty group keeps wait accounting exact
                }

                const float* As = smf + (it & 3) * ST_F;
                const float* Bs = As + TA_F;

#pragma unroll
                for (int ks = 0; ks < 4; ks++) {
                    const int kc = ks * 8 + tig;

                    uint32_t bh[3][2], bl[3][2];
#pragma unroll
                    for (int nf = 0; nf < 3; nf++) {
                        const int bb = (wn * 24 + nf * 8 + gid) * LDA + kc;
                        tf32_split(Bs[bb],     bh[nf][0], bl[nf][0]);
                        tf32_split(Bs[bb + 4], bh[nf][1], bl[nf][1]);
                    }
#pragma unroll
                    for (int mf = 0; mf < 4; mf++) {
                        const int ab = (wm * 64 + mf * 16 + gid) * LDA + kc;
                        uint32_t ah[4], al[4];
                        tf32_split(As[ab],               ah[0], al[0]);
                        tf32_split(As[ab + 8 * LDA],     ah[1], al[1]);
                        tf32_split(As[ab + 4],           ah[2], al[2]);
                        tf32_split(As[ab + 8 * LDA + 4], ah[3], al[3]);
#pragma unroll
                        for (int nf = 0; nf < 3; nf++) {
                            MMA8(acc[mf][nf], al[0], al[1], al[2], al[3],
                                 bh[nf][0], bh[nf][1]);
                            MMA8(acc[mf][nf], ah[0], ah[1], ah[2], ah[3],
                                 bl[nf][0], bl[nf][1]);
                            MMA8(acc[mf][nf], ah[0], ah[1], ah[2], ah[3],
                                 bh[nf][0], bh[nf][1]);
                        }
                    }
                }
            }
#undef STAGE

            // epilogue: registers -> g_gh
#pragma unroll
            for (int mf = 0; mf < 4; mf++) {
                const int row = m0 + wm * 64 + mf * 16 + gid;
#pragma unroll
                for (int nf = 0; nf < 3; nf++) {
                    const int col = n0 + wn * 24 + nf * 8 + 2 * tig;
                    float2 v0 = make_float2(acc[mf][nf][0], acc[mf][nf][1]);
                    float2 v1 = make_float2(acc[mf][nf][2], acc[mf][nf][3]);
                    *(float2*)(g_gh + (size_t)row * NG + col)       = v0;
                    *(float2*)(g_gh + (size_t)(row + 8) * NG + col) = v1;
                }
            }
        }
        grid_bar();   // g_gh ready everywhere

        // ========== fused gate + logits: 2 full rows per block ==========
        {
            float* hnew = g_h + (size_t)par * NB * NH;
#pragma unroll 1
            for (int b = blk; b < NB; b += NBLK) {   // exactly 2 rows
                float hreg[8];
                float lacc[NO];
#pragma unroll
                for (int o = 0; o < NO; o++) lacc[o] = 0.f;

                const int s = (t > 0) ? s_sel[b] : 0;

#pragma unroll
                for (int i = 0; i < 8; i++) {
                    const int j = tid + i * NTHR;

                    float ghr = g_gh[(size_t)b * NG + j]          + b_hh[j];
                    float ghz = g_gh[(size_t)b * NG + NH + j]     + b_hh[NH + j];
                    float ghn = g_gh[(size_t)b * NG + 2 * NH + j] + b_hh[2 * NH + j];
                    float gir = b_ih[j], giz = b_ih[NH + j], gin = b_ih[2 * NH + j];

                    if (t == 0) {
#pragma unroll
                        for (int o = 0; o < NO; o++) {
                            float xv = fmaxf(target[(size_t)b * NT * NO + o], 0.f);
                            gir = fmaf(xv, W_ih[(size_t)j * NO + o], gir);
                            giz = fmaf(xv, W_ih[(size_t)(NH + j) * NO + o], giz);
                            gin = fmaf(xv, W_ih[(size_t)(2 * NH + j) * NO + o], gin);
                        }
                    } else if (s >= 0) {
                        gir += W_ih[(size_t)j * NO + s];
                        giz += W_ih[(size_t)(NH + j) * NO + s];
                        gin += W_ih[(size_t)(2 * NH + j) * NO + s];
                    }

                    float r  = 1.f / (1.f + expf(-(gir + ghr)));
                    float z  = 1.f / (1.f + expf(-(giz + ghz)));
                    float n  = tanhf(gin + r * ghn);
                    float hp = hprev[(size_t)b * NH + j];
                    float hv = (1.f - z) * n + z * hp;
                    hreg[i] = hv;
                    hnew[(size_t)b * NH + j] = hv;

                    // logits partial: h stays in registers
#pragma unroll
                    for (int o = 0; o < NO; o++)
                        lacc[o] = fmaf(hv, W_out[(size_t)o * NH + j], lacc[o]);
                }

                // reduce 14 partials over 256 threads
#pragma unroll
                for (int o = 0; o < NO; o++) {
#pragma unroll
                    for (int off = 16; off > 0; off >>= 1)
                        lacc[o] += __shfl_xor_sync(0xffffffffu, lacc[o], off);
                }
                if (lid == 0) {
#pragma unroll
                    for (int o = 0; o < NO; o++) s_red[w][o] = lacc[o];
                }
                __syncthreads();
                if (tid < NO) {
                    float l = b_out[tid];
#pragma unroll
                    for (int ww = 0; ww < 8; ww++) l += s_red[ww][tid];
                    s_l[tid] = l;
                }
                __syncthreads();
                if (tid == 0) {
                    float l[NO];
                    float m = -1e30f;
#pragma unroll
                    for (int o = 0; o < NO; o++) { l[o] = s_l[o]; m = fmaxf(m, l[o]); }
                    int   bi = 0;
                    float bv = l[0];
#pragma unroll
                    for (int o = 1; o < NO; o++)
                        if (l[o] > bv) { bv = l[o]; bi = o; }   // first-max = jnp.argmax
                    float ssum = 0.f;
#pragma unroll
                    for (int o = 0; o < NO; o++) ssum += expf(l[o] - m);
                    float lse = m + logf(ssum);
                    float* dst = out + ((size_t)b * NT + t) * NO;
#pragma unroll
                    for (int o = 0; o < NO; o++) dst[o] = l[o] - lse;
                    g_topi[b] = bi;
                }
                __syncthreads();
            }
        }
        grid_bar();   // h(t), topi(t) ready everywhere
    }

    // ---------------- tail: append h_final ------------------------------
    {
        const float* hf = g_h + (size_t)((NT - 1) & 1) * NB * NH;
        float* tail = out + (size_t)NB * NT * NO;
        for (int i = gtid; i < NB * NH / 4; i += NTOT) {
            float4 v = *(const float4*)(hf + (size_t)i * 4);
            *(float4*)(tail + (size_t)i * 4) = v;
        }
    }
}

// =====================================================================
extern "C" void kernel_launch(void* const* d_in, const int* in_sizes, int n_in,
                              void* d_out, int out_size)
{
    // inputs: 0 encoder_outputs (unused), 1 encoder_hidden, 2 target_tensor,
    //         3 W_ih, 4 W_hh, 5 b_ih, 6 b_hh, 7 W_out, 8 b_out
    const float* enc_h  = (const float*)d_in[1];
    const float* target = (const float*)d_in[2];
    const float* W_ih   = (const float*)d_in[3];
    const float* W_hh   = (const float*)d_in[4];
    const float* b_ih   = (const float*)d_in[5];
    const float* b_hh   = (const float*)d_in[6];
    const float* W_out  = (const float*)d_in[7];
    const float* b_out  = (const float*)d_in[8];
    float* out = (float*)d_out;

    cudaFuncSetAttribute(decoder_kernel,
                         cudaFuncAttributeMaxDynamicSharedMemorySize, SMEM_DYN);

    decoder_kernel<<<NBLK, NTHR, SMEM_DYN>>>(enc_h, target, W_ih, W_hh,
                                             b_ih, b_hh, W_out, b_out, out);
}

// round 13
// speedup vs baseline: 1.4232x; 1.0693x over previous
#include <cuda_runtime.h>
#include <cstdint>

#define NB 256   // batch
#define NH 2048  // hidden
#define NG 6144  // 3*H
#define NT 512   // time steps
#define NO 14    // output classes

#define NBLK 128 // persistent blocks, tile grid 2 (M) x 64 (N)
#define NTHR 256 // 8 warps: 2x4 warp grid, warp tile 64x24
#define BK 32    // k per staged iteration
#define KITERS (NH / BK)
#define LDA 36   // smem row stride floats (36 mod 32 = 4 -> conflict-free frags)

#define TM 128   // block tile M
#define TN 96    // block tile N
#define TA_F (TM * LDA)             // 4608 words per A tile (hi or lo)
#define TB_F (TN * LDA)             // 3456 words
#define ST_F (2 * TA_F + TB_F)      // 12672 words per stage (Ahi | Alo | B)
#define NSTG 4
#define SMEM_DYN (NSTG * ST_F * 4)  // 202752 B

// ---- device-global scratch (no allocations allowed) ----
__device__ __align__(16) float    g_gh[NB * NG];        // gh scratch, 6 MB
__device__ __align__(16) float    g_h[2 * NB * NH];     // fp32 hidden, ping-pong
__device__ __align__(16) uint32_t g_hhi[2 * NB * NH];   // tf32 hi of h, ping-pong
__device__ __align__(16) uint32_t g_hlo[2 * NB * NH];   // tf32 lo of h, ping-pong
__device__ int   g_topi[NB];
__device__ unsigned g_bar_count;
__device__ unsigned g_bar_gen;

// =====================================================================
// helpers
// =====================================================================
__device__ __forceinline__ uint32_t smem_u32(const void* p) {
    uint32_t a;
    asm("{ .reg .u64 t; cvta.to.shared.u64 t, %1; cvt.u32.u64 %0, t; }"
        : "=r"(a) : "l"(p));
    return a;
}

#define CP_ASYNC16(saddr, gptr) \
    asm volatile("cp.async.cg.shared.global [%0], [%1], 16;" \
                 :: "r"(saddr), "l"(gptr) : "memory")
#define CP_COMMIT()  asm volatile("cp.async.commit_group;" ::: "memory")
#define CP_WAIT(n)   asm volatile("cp.async.wait_group %0;" :: "n"(n) : "memory")

// tf32 split: v = hi + lo, both tf32-representable (round-to-nearest)
__device__ __forceinline__ void tf32_split(float v, uint32_t& hi, uint32_t& lo) {
    asm("cvt.rna.tf32.f32 %0, %1;" : "=r"(hi) : "f"(v));
    float rl = v - __uint_as_float(hi);
    asm("cvt.rna.tf32.f32 %0, %1;" : "=r"(lo) : "f"(rl));
}

// C += A(16x8,row) * B(8x8,col)   tf32 -> f32
#define MMA8(c, a0, a1, a2, a3, b0, b1) \
    asm volatile("mma.sync.aligned.m16n8k8.row.col.f32.tf32.tf32.f32 " \
        "{%0,%1,%2,%3},{%4,%5,%6,%7},{%8,%9},{%0,%1,%2,%3};" \
        : "+f"((c)[0]), "+f"((c)[1]), "+f"((c)[2]), "+f"((c)[3]) \
        : "r"(a0), "r"(a1), "r"(a2), "r"(a3), "r"(b0), "r"(b1))

// =====================================================================
// Software grid barrier (all NBLK blocks co-resident; 128 <= 148 SMs)
// =====================================================================
__device__ __forceinline__ void grid_bar()
{
    __syncthreads();
    if (threadIdx.x == 0) {
        __threadfence();
        unsigned gen = *(volatile unsigned*)&g_bar_gen;
        unsigned arr = atomicAdd(&g_bar_count, 1u);
        if (arr == NBLK - 1) {
            *(volatile unsigned*)&g_bar_count = 0u;
            __threadfence();
            *(volatile unsigned*)&g_bar_gen = gen + 1u;
        } else {
            while (*(volatile unsigned*)&g_bar_gen == gen) { __nanosleep(64); }
        }
        __threadfence();
    }
    __syncthreads();
}

// =====================================================================
// persistent kernel for the full 512-step decode
// =====================================================================
__global__ __launch_bounds__(NTHR, 1)
void decoder_kernel(const float* __restrict__ enc_h,
                    const float* __restrict__ target,
                    const float* __restrict__ W_ih,
                    const float* __restrict__ W_hh,
                    const float* __restrict__ b_ih,
                    const float* __restrict__ b_hh,
                    const float* __restrict__ W_out,
                    const float* __restrict__ b_out,
                    float* __restrict__ out)
{
    extern __shared__ float smf[];            // NSTG stages of (Ahi | Alo | B)
    __shared__ int   s_sel[NB];               // block-local feedback select
    __shared__ float s_red[8][NO];            // logits cross-warp reduce
    __shared__ float s_l[NO];

    const int tid = threadIdx.x;
    const int w   = tid >> 5;        // warp 0..7
    const int lid = tid & 31;
    const int gid = lid >> 2;        // 0..7
    const int tig = lid & 3;         // 0..3
    const int wm  = w >> 2;          // 0..1 : warp row (64 M)
    const int wn  = w & 3;           // 0..3 : warp col (24 N)
    const int blk  = blockIdx.x;
    const int m0   = (blk >> 6) * TM;     // 0 or 128
    const int n0   = (blk & 63) * TN;     // 0..6048
    const int gtid = blk * NTHR + tid;
    const int NTOT = NBLK * NTHR;

    const uint32_t sb = smem_u32(smf);

    // ------------- prologue: split enc_h into slot 1 ---------------------
    // (t=0 reads slot (1 - par) = 1)
    for (size_t i = (size_t)gtid * 4; i < (size_t)NB * NH; i += (size_t)NTOT * 4) {
        float4 v = *(const float4*)(enc_h + i);
        uint32_t h0, l0, h1, l1, h2, l2, h3, l3;
        tf32_split(v.x, h0, l0); tf32_split(v.y, h1, l1);
        tf32_split(v.z, h2, l2); tf32_split(v.w, h3, l3);
        *(uint4*)(g_hhi + (size_t)NB * NH + i) = make_uint4(h0, h1, h2, h3);
        *(uint4*)(g_hlo + (size_t)NB * NH + i) = make_uint4(l0, l1, l2, l3);
    }
    grid_bar();

    for (int t = 0; t < NT; t++) {
        const int par = t & 1;
        const float* hprev = (t == 0) ? enc_h : (g_h + (size_t)(1 - par) * NB * NH);
        const size_t aslot = (size_t)(1 - par) * NB * NH;

        // ================= GEMM: g_gh = hprev @ W_hh^T ==================
        {
            const uint32_t* Aih = g_hhi + aslot + (size_t)m0 * NH;
            const uint32_t* Ail = g_hlo + aslot + (size_t)m0 * NH;
            const float*    Bg  = W_hh  + (size_t)n0 * NH;

            float acc[4][3][4];
#pragma unroll
            for (int i = 0; i < 4; i++)
#pragma unroll
                for (int j = 0; j < 3; j++)
#pragma unroll
                    for (int c = 0; c < 4; c++) acc[i][j][c] = 0.f;

            // stage(bs, k0): Ahi 1024 + Alo 1024 + B 768 float4 = 2816 = 11*256
#define STAGE(bs, k0) do {                                                    \
    const uint32_t sst = sb + (uint32_t)(bs) * (ST_F * 4u);                   \
    _Pragma("unroll")                                                         \
    for (int i = 0; i < 11; i++) {                                            \
        int idx = tid + i * NTHR;                                             \
        if (idx < 1024) {                                                     \
            int row = idx >> 3, c4 = (idx & 7) << 2;                          \
            CP_ASYNC16(sst + (uint32_t)(row * LDA + c4) * 4u,                 \
                       Aih + (size_t)row * NH + (k0) + c4);                   \
        } else if (idx < 2048) {                                              \
            int jx = idx - 1024;                                              \
            int row = jx >> 3, c4 = (jx & 7) << 2;                            \
            CP_ASYNC16(sst + (uint32_t)(TA_F + row * LDA + c4) * 4u,          \
                       Ail + (size_t)row * NH + (k0) + c4);                   \
        } else {                                                              \
            int jx = idx - 2048;                                              \
            int row = jx >> 3, c4 = (jx & 7) << 2;                            \
            CP_ASYNC16(sst + (uint32_t)(2 * TA_F + row * LDA + c4) * 4u,      \
                       Bg + (size_t)row * NH + (k0) + c4);                    \
        }                                                                     \
    }                                                                         \
    CP_COMMIT();                                                              \
} while (0)

            // prologue: stages 0..2 in flight (3 committed groups)
            STAGE(0, 0);
            STAGE(1, BK);
            STAGE(2, 2 * BK);

            // block-local scan of topi(t-1) -> s_sel (warp 0)
            if (t > 0 && w == 0) {
                int tp[8]; int hit[8]; unsigned chunk = 0;
#pragma unroll
                for (int i = 0; i < 8; i++) {
                    tp[i]  = g_topi[lid * 8 + i];
                    hit[i] = (tp[i] == NO - 1);
                    chunk |= (unsigned)hit[i];
                }
                unsigned inc = chunk;
#pragma unroll
                for (int off = 1; off < 32; off <<= 1) {
                    unsigned v = __shfl_up_sync(0xffffffffu, inc, off);
                    if (lid >= off) inc |= v;
                }
                unsigned excl = __shfl_up_sync(0xffffffffu, inc, 1);
                unsigned run  = (lid == 0) ? 0u : excl;
#pragma unroll
                for (int i = 0; i < 8; i++) {
                    int alive = !(run | (unsigned)hit[i]);
                    s_sel[lid * 8 + i] = alive ? tp[i] : -1;
                    run |= (unsigned)hit[i];
                }
            }

            for (int it = 0; it < KITERS; it++) {
                CP_WAIT(2);           // stage 'it' landed (this thread)
                __syncthreads();      // all threads: data visible, old buf free
                if (it + 3 < KITERS) {
                    STAGE((it + 3) & 3, (it + 3) * BK);
                } else {
                    CP_COMMIT();      // empty group keeps wait accounting exact
                }

                const uint32_t* Ah = (const uint32_t*)(smf + (it & 3) * ST_F);
                const uint32_t* Al = Ah + TA_F;
                const float*    Bs = (const float*)(Ah + 2 * TA_F);

#pragma unroll
                for (int ks = 0; ks < 4; ks++) {
                    const int kc = ks * 8 + tig;

                    uint32_t bh[3][2], bl[3][2];
#pragma unroll
                    for (int nf = 0; nf < 3; nf++) {
                        const int bb = (wn * 24 + nf * 8 + gid) * LDA + kc;
                        tf32_split(Bs[bb],     bh[nf][0], bl[nf][0]);
                        tf32_split(Bs[bb + 4], bh[nf][1], bl[nf][1]);
                    }
#pragma unroll
                    for (int mf = 0; mf < 4; mf++) {
                        const int ab = (wm * 64 + mf * 16 + gid) * LDA + kc;
                        uint32_t ah[4], al[4];
                        ah[0] = Ah[ab];                al[0] = Al[ab];
                        ah[1] = Ah[ab + 8 * LDA];      al[1] = Al[ab + 8 * LDA];
                        ah[2] = Ah[ab + 4];            al[2] = Al[ab + 4];
                        ah[3] = Ah[ab + 8 * LDA + 4];  al[3] = Al[ab + 8 * LDA + 4];
#pragma unroll
                        for (int nf = 0; nf < 3; nf++) {
                            MMA8(acc[mf][nf], al[0], al[1], al[2], al[3],
                                 bh[nf][0], bh[nf][1]);
                            MMA8(acc[mf][nf], ah[0], ah[1], ah[2], ah[3],
                                 bl[nf][0], bl[nf][1]);
                            MMA8(acc[mf][nf], ah[0], ah[1], ah[2], ah[3],
                                 bh[nf][0], bh[nf][1]);
                        }
                    }
                }
            }
#undef STAGE

            // epilogue: registers -> g_gh
#pragma unroll
            for (int mf = 0; mf < 4; mf++) {
                const int row = m0 + wm * 64 + mf * 16 + gid;
#pragma unroll
                for (int nf = 0; nf < 3; nf++) {
                    const int col = n0 + wn * 24 + nf * 8 + 2 * tig;
                    float2 v0 = make_float2(acc[mf][nf][0], acc[mf][nf][1]);
                    float2 v1 = make_float2(acc[mf][nf][2], acc[mf][nf][3]);
                    *(float2*)(g_gh + (size_t)row * NG + col)       = v0;
                    *(float2*)(g_gh + (size_t)(row + 8) * NG + col) = v1;
                }
            }
        }
        grid_bar();   // g_gh ready everywhere

        // ========== fused gate + logits: 2 full rows per block ==========
        {
            float* hnew = g_h + (size_t)par * NB * NH;
            const size_t wslot = (size_t)par * NB * NH;
#pragma unroll 1
            for (int b = blk; b < NB; b += NBLK) {   // exactly 2 rows
                float lacc[NO];
#pragma unroll
                for (int o = 0; o < NO; o++) lacc[o] = 0.f;

                const int s = (t > 0) ? s_sel[b] : 0;

#pragma unroll
                for (int i = 0; i < 8; i++) {
                    const int j = tid + i * NTHR;

                    float ghr = g_gh[(size_t)b * NG + j]          + b_hh[j];
                    float ghz = g_gh[(size_t)b * NG + NH + j]     + b_hh[NH + j];
                    float ghn = g_gh[(size_t)b * NG + 2 * NH + j] + b_hh[2 * NH + j];
                    float gir = b_ih[j], giz = b_ih[NH + j], gin = b_ih[2 * NH + j];

                    if (t == 0) {
#pragma unroll
                        for (int o = 0; o < NO; o++) {
                            float xv = fmaxf(target[(size_t)b * NT * NO + o], 0.f);
                            gir = fmaf(xv, W_ih[(size_t)j * NO + o], gir);
                            giz = fmaf(xv, W_ih[(size_t)(NH + j) * NO + o], giz);
                            gin = fmaf(xv, W_ih[(size_t)(2 * NH + j) * NO + o], gin);
                        }
                    } else if (s >= 0) {
                        gir += W_ih[(size_t)j * NO + s];
                        giz += W_ih[(size_t)(NH + j) * NO + s];
                        gin += W_ih[(size_t)(2 * NH + j) * NO + s];
                    }

                    float r  = 1.f / (1.f + expf(-(gir + ghr)));
                    float z  = 1.f / (1.f + expf(-(giz + ghz)));
                    float n  = tanhf(gin + r * ghn);
                    float hp = hprev[(size_t)b * NH + j];
                    float hv = (1.f - z) * n + z * hp;
                    hnew[(size_t)b * NH + j] = hv;

                    // split h for next step's GEMM A operand (coalesced)
                    uint32_t shi, slo;
                    tf32_split(hv, shi, slo);
                    g_hhi[wslot + (size_t)b * NH + j] = shi;
                    g_hlo[wslot + (size_t)b * NH + j] = slo;

                    // logits partial: h stays in registers
#pragma unroll
                    for (int o = 0; o < NO; o++)
                        lacc[o] = fmaf(hv, W_out[(size_t)o * NH + j], lacc[o]);
                }

                // reduce 14 partials over 256 threads
#pragma unroll
                for (int o = 0; o < NO; o++) {
#pragma unroll
                    for (int off = 16; off > 0; off >>= 1)
                        lacc[o] += __shfl_xor_sync(0xffffffffu, lacc[o], off);
                }
                if (lid == 0) {
#pragma unroll
                    for (int o = 0; o < NO; o++) s_red[w][o] = lacc[o];
                }
                __syncthreads();
                if (tid < NO) {
                    float l = b_out[tid];
#pragma unroll
                    for (int ww = 0; ww < 8; ww++) l += s_red[ww][tid];
                    s_l[tid] = l;
                }
                __syncthreads();
                if (tid == 0) {
                    float l[NO];
                    float m = -1e30f;
#pragma unroll
                    for (int o = 0; o < NO; o++) { l[o] = s_l[o]; m = fmaxf(m, l[o]); }
                    int   bi = 0;
                    float bv = l[0];
#pragma unroll
                    for (int o = 1; o < NO; o++)
                        if (l[o] > bv) { bv = l[o]; bi = o; }   // first-max = jnp.argmax
                    float ssum = 0.f;
#pragma unroll
                    for (int o = 0; o < NO; o++) ssum += expf(l[o] - m);
                    float lse = m + logf(ssum);
                    float* dst = out + ((size_t)b * NT + t) * NO;
#pragma unroll
                    for (int o = 0; o < NO; o++) dst[o] = l[o] - lse;
                    g_topi[b] = bi;
                }
                __syncthreads();
            }
        }
        grid_bar();   // h(t), topi(t), splits ready everywhere
    }

    // ---------------- tail: append h_final ------------------------------
    {
        const float* hf = g_h + (size_t)((NT - 1) & 1) * NB * NH;
        float* tail = out + (size_t)NB * NT * NO;
        for (int i = gtid; i < NB * NH / 4; i += NTOT) {
            float4 v = *(const float4*)(hf + (size_t)i * 4);
            *(float4*)(tail + (size_t)i * 4) = v;
        }
    }
}

// =====================================================================
extern "C" void kernel_launch(void* const* d_in, const int* in_sizes, int n_in,
                              void* d_out, int out_size)
{
    // inputs: 0 encoder_outputs (unused), 1 encoder_hidden, 2 target_tensor,
    //         3 W_ih, 4 W_hh, 5 b_ih, 6 b_hh, 7 W_out, 8 b_out
    const float* enc_h  = (const float*)d_in[1];
    const float* target = (const float*)d_in[2];
    const float* W_ih   = (const float*)d_in[3];
    const float* W_hh   = (const float*)d_in[4];
    const float* b_ih   = (const float*)d_in[5];
    const float* b_hh   = (const float*)d_in[6];
    const float* W_out  = (const float*)d_in[7];
    const float* b_out  = (const float*)d_in[8];
    float* out = (float*)d_out;

    cudaFuncSetAttribute(decoder_kernel,
                         cudaFuncAttributeMaxDynamicSharedMemorySize, SMEM_DYN);

    decoder_kernel<<<NBLK, NTHR, SMEM_DYN>>>(enc_h, target, W_ih, W_hh,
                                             b_ih, b_hh, W_out, b_out, out);
}